// round 2
// baseline (speedup 1.0000x reference)
#include <cuda_runtime.h>
#include <math.h>

// ---------------------------------------------------------------------------
// GraphTransformer layer: N=50000 nodes, E=600000 edges, C=128, H=8, Dh=16
// Round 2: fix int32/int64 edge_index ambiguity (device-side detection) and
// shared-memory float4 alignment. fp32 SIMT pipeline, GEMM-bound (~131 GF).
// ---------------------------------------------------------------------------

#define N_MAX 50000
#define E_MAX 600000

// Scratch (device globals; allocation-free per harness rules)
__device__ float g_hln[(size_t)N_MAX * 128];   // node LN1 out / h_attn / hn (reused)
__device__ float g_qkv[(size_t)N_MAX * 384];   // q | k | v interleaved per row
__device__ float g_eln[(size_t)E_MAX * 128];   // edge LN out (LN1, later LN2)
__device__ float g_ep [(size_t)E_MAX * 128];   // ep, then alpha in-place
__device__ float g_dist[(size_t)E_MAX];
__device__ float g_wV [(size_t)N_MAX * 128];
__device__ float g_z  [(size_t)N_MAX * 8];
__device__ float g_t  [(size_t)E_MAX * 256];   // FFN hidden (nodes then edges)
__device__ int   g_is64;                        // edge_index dtype flag

// ---------------------------------------------------------------------------
// Detect whether edge_index is int64 (odd int32 words all zero) or int32.
// ---------------------------------------------------------------------------
__global__ void detect_kernel(const int* __restrict__ ei32)
{
    if (threadIdx.x == 0 && blockIdx.x == 0) {
        int any = 0;
        #pragma unroll 8
        for (int i = 0; i < 64; i++) any |= ei32[2 * i + 1];
        g_is64 = (any == 0) ? 1 : 0;
    }
}

__device__ __forceinline__ int edge_idx(const void* __restrict__ ei, long long pos)
{
    if (g_is64) return (int)((const long long*)ei)[pos];
    return ((const int*)ei)[pos];
}

// ---------------------------------------------------------------------------
// LayerNorm: one warp per row of 128
// ---------------------------------------------------------------------------
__global__ void ln_kernel(const float* __restrict__ x,
                          const float* __restrict__ g,
                          const float* __restrict__ b,
                          float* __restrict__ out, int M)
{
    int w = (blockIdx.x * blockDim.x + threadIdx.x) >> 5;
    int lane = threadIdx.x & 31;
    if (w >= M) return;
    float4 v = *(const float4*)(x + (size_t)w * 128 + lane * 4);
    float s  = v.x + v.y + v.z + v.w;
    float sq = v.x*v.x + v.y*v.y + v.z*v.z + v.w*v.w;
    #pragma unroll
    for (int o = 16; o; o >>= 1) {
        s  += __shfl_xor_sync(0xffffffffu, s,  o);
        sq += __shfl_xor_sync(0xffffffffu, sq, o);
    }
    float mu  = s * (1.0f / 128.0f);
    float var = sq * (1.0f / 128.0f) - mu * mu;
    float rs  = rsqrtf(var + 1e-5f);
    float4 gv = *(const float4*)(g + lane * 4);
    float4 bv = *(const float4*)(b + lane * 4);
    float4 o4;
    o4.x = (v.x - mu) * rs * gv.x + bv.x;
    o4.y = (v.y - mu) * rs * gv.y + bv.y;
    o4.z = (v.z - mu) * rs * gv.z + bv.z;
    o4.w = (v.w - mu) * rs * gv.w + bv.w;
    *(float4*)(out + (size_t)w * 128 + lane * 4) = o4;
}

// ---------------------------------------------------------------------------
// Pairwise distance per edge: 0.1 * || coords[row] - coords[col] ||
// ---------------------------------------------------------------------------
__global__ void dist_kernel(const float* __restrict__ coords,
                            const void* __restrict__ ei,
                            float* __restrict__ dist, int E)
{
    int e = blockIdx.x * blockDim.x + threadIdx.x;
    if (e >= E) return;
    int r = edge_idx(ei, e);
    int c = edge_idx(ei, (long long)E + e);
    float dx = coords[r * 3 + 0] - coords[c * 3 + 0];
    float dy = coords[r * 3 + 1] - coords[c * 3 + 1];
    float dz = coords[r * 3 + 2] - coords[c * 3 + 2];
    dist[e] = 0.1f * sqrtf(dx * dx + dy * dy + dz * dz);
}

__global__ void fill0_kernel(float* __restrict__ p, size_t n)
{
    size_t i = (size_t)blockIdx.x * blockDim.x + threadIdx.x;
    if (i < n) p[i] = 0.0f;
}

// ---------------------------------------------------------------------------
// Generic tiled SGEMM: C = epi(A[M,K] @ W[K,Nw])
// BM=128, BN=64, BK=16, 256 threads, 8x4 per-thread microtile.
// Epilogue: + bias[n], + r1m[m]*r1n[n], SiLU, + residual[m*ldr+n].
// ---------------------------------------------------------------------------
#define BM 128
#define BN 64
#define BK 16

__global__ void __launch_bounds__(256, 2) sgemm_kernel(
    const float* __restrict__ A, const float* __restrict__ W,
    float* __restrict__ Cout,
    int M, int K, int Nw, int ldc,
    const float* __restrict__ bias,
    const float* __restrict__ resid, int ldr,
    const float* __restrict__ r1m, const float* __restrict__ r1n,
    int act)
{
    __shared__ __align__(16) float As[BK][BM + 4];
    __shared__ __align__(16) float Bs[BK][BN];

    int tid = threadIdx.x;
    int m0 = blockIdx.x * BM;
    int n0 = blockIdx.y * BN;

    int trow = tid >> 4;          // 0..15 -> 8 rows each
    int tcol = tid & 15;          // 0..15 -> 4 cols each

    int ar = tid >> 2;            // 0..63
    int ac = (tid & 3) << 2;      // 0,4,8,12
    int br = tid >> 4;            // 0..15
    int bc = (tid & 15) << 2;     // 0..60

    float acc[8][4];
    #pragma unroll
    for (int i = 0; i < 8; i++)
        #pragma unroll
        for (int j = 0; j < 4; j++) acc[i][j] = 0.0f;

    for (int k0 = 0; k0 < K; k0 += BK) {
        #pragma unroll
        for (int h = 0; h < 2; h++) {
            int m = m0 + ar + h * 64;
            float4 a4 = make_float4(0.f, 0.f, 0.f, 0.f);
            if (m < M) a4 = *(const float4*)(A + (size_t)m * K + k0 + ac);
            As[ac + 0][ar + h * 64] = a4.x;
            As[ac + 1][ar + h * 64] = a4.y;
            As[ac + 2][ar + h * 64] = a4.z;
            As[ac + 3][ar + h * 64] = a4.w;
        }
        float4 b4 = *(const float4*)(W + (size_t)(k0 + br) * Nw + n0 + bc);
        *(float4*)&Bs[br][bc] = b4;
        __syncthreads();

        #pragma unroll
        for (int k = 0; k < BK; k++) {
            float af[8], bf[4];
            *(float4*)&af[0] = *(const float4*)&As[k][trow * 8];
            *(float4*)&af[4] = *(const float4*)&As[k][trow * 8 + 4];
            *(float4*)&bf[0] = *(const float4*)&Bs[k][tcol * 4];
            #pragma unroll
            for (int i = 0; i < 8; i++)
                #pragma unroll
                for (int j = 0; j < 4; j++)
                    acc[i][j] = fmaf(af[i], bf[j], acc[i][j]);
        }
        __syncthreads();
    }

    #pragma unroll
    for (int i = 0; i < 8; i++) {
        int m = m0 + trow * 8 + i;
        if (m >= M) continue;
        float r1 = r1m ? r1m[m] : 0.0f;
        #pragma unroll
        for (int j = 0; j < 4; j++) {
            int n = n0 + tcol * 4 + j;
            float v = acc[i][j];
            if (bias) v += bias[n];
            if (r1m)  v += r1 * r1n[n];
            if (act)  v = v / (1.0f + expf(-v));   // SiLU
            if (resid) v += resid[(size_t)m * ldr + n];
            Cout[(size_t)m * ldc + n] = v;
        }
    }
}

// ---------------------------------------------------------------------------
// Edge attention: one warp per edge.
//   alpha = clip(k[row]*q[col]/4, +-5) * ep          (written in-place over ep)
//   ax    = exp(clip(sum_Dh alpha, +-5))             (per head)
//   wV[col] += v[row]*ax ; z[col] += ax              (atomics)
// ---------------------------------------------------------------------------
__global__ void attn_edge_kernel(const float* __restrict__ qkv,
                                 float* __restrict__ ep_alpha,
                                 const void* __restrict__ ei,
                                 float* __restrict__ wV,
                                 float* __restrict__ z,
                                 int E)
{
    int w = (blockIdx.x * blockDim.x + threadIdx.x) >> 5;
    int lane = threadIdx.x & 31;
    if (w >= E) return;
    int r = edge_idx(ei, w);
    int c = edge_idx(ei, (long long)E + w);

    float4 q4 = *(const float4*)(qkv + (size_t)c * 384 + lane * 4);
    float4 k4 = *(const float4*)(qkv + (size_t)r * 384 + 128 + lane * 4);
    float4 v4 = *(const float4*)(qkv + (size_t)r * 384 + 256 + lane * 4);
    float4 e4 = *(const float4*)(ep_alpha + (size_t)w * 128 + lane * 4);

    float4 a4;
    a4.x = fminf(fmaxf(k4.x * q4.x * 0.25f, -5.0f), 5.0f) * e4.x;
    a4.y = fminf(fmaxf(k4.y * q4.y * 0.25f, -5.0f), 5.0f) * e4.y;
    a4.z = fminf(fmaxf(k4.z * q4.z * 0.25f, -5.0f), 5.0f) * e4.z;
    a4.w = fminf(fmaxf(k4.w * q4.w * 0.25f, -5.0f), 5.0f) * e4.w;
    *(float4*)(ep_alpha + (size_t)w * 128 + lane * 4) = a4;

    // per-head sum over Dh=16 (4 lanes x 4 values)
    float hs = a4.x + a4.y + a4.z + a4.w;
    hs += __shfl_xor_sync(0xffffffffu, hs, 1);
    hs += __shfl_xor_sync(0xffffffffu, hs, 2);
    float ax = expf(fminf(fmaxf(hs, -5.0f), 5.0f));

    float* wvp = wV + (size_t)c * 128 + lane * 4;
    atomicAdd(wvp + 0, v4.x * ax);
    atomicAdd(wvp + 1, v4.y * ax);
    atomicAdd(wvp + 2, v4.z * ax);
    atomicAdd(wvp + 3, v4.w * ax);
    if ((lane & 3) == 0)
        atomicAdd(z + (size_t)c * 8 + (lane >> 2), ax);
}

__global__ void hattn_kernel(const float* __restrict__ wV,
                             const float* __restrict__ z,
                             float* __restrict__ out, int N)
{
    int i = blockIdx.x * blockDim.x + threadIdx.x;
    if (i >= N * 128) return;
    int n = i >> 7;
    int h = (i & 127) >> 4;
    out[i] = wV[i] / (z[(size_t)n * 8 + h] + 1e-6f);
}

// ---------------------------------------------------------------------------
// Launch
// ---------------------------------------------------------------------------
extern "C" void kernel_launch(void* const* d_in, const int* in_sizes, int n_in,
                              void* d_out, int out_size)
{
    const float* node_feats = (const float*)d_in[0];
    const float* edge_feats = (const float*)d_in[1];
    const float* coords     = (const float*)d_in[2];
    const void*  ei         = d_in[3];
    const float* Wq   = (const float*)d_in[4];
    const float* Wk   = (const float*)d_in[5];
    const float* Wv   = (const float*)d_in[6];
    const float* We   = (const float*)d_in[7];
    const float* Wo_n = (const float*)d_in[8];
    const float* bo_n = (const float*)d_in[9];
    const float* Wo_e = (const float*)d_in[10];
    const float* bo_e = (const float*)d_in[11];
    const float* ln1n_g = (const float*)d_in[12];
    const float* ln1n_b = (const float*)d_in[13];
    const float* ln1e_g = (const float*)d_in[14];
    const float* ln1e_b = (const float*)d_in[15];
    const float* ln2n_g = (const float*)d_in[16];
    const float* ln2n_b = (const float*)d_in[17];
    const float* ln2e_g = (const float*)d_in[18];
    const float* ln2e_b = (const float*)d_in[19];
    const float* Wn1 = (const float*)d_in[20];
    const float* Wn2 = (const float*)d_in[21];
    const float* We1 = (const float*)d_in[22];
    const float* We2 = (const float*)d_in[23];

    int N = in_sizes[0] / 128;
    int E = in_sizes[1] / 128;

    float* out   = (float*)d_out;
    float* out_n = out;
    float* out_e = out + (size_t)N * 128;

    float *p_hln, *p_qkv, *p_eln, *p_ep, *p_dist, *p_wV, *p_z, *p_t;
    cudaGetSymbolAddress((void**)&p_hln,  g_hln);
    cudaGetSymbolAddress((void**)&p_qkv,  g_qkv);
    cudaGetSymbolAddress((void**)&p_eln,  g_eln);
    cudaGetSymbolAddress((void**)&p_ep,   g_ep);
    cudaGetSymbolAddress((void**)&p_dist, g_dist);
    cudaGetSymbolAddress((void**)&p_wV,   g_wV);
    cudaGetSymbolAddress((void**)&p_z,    g_z);
    cudaGetSymbolAddress((void**)&p_t,    g_t);

    dim3 blk(256);

    // 0. detect edge_index dtype (int32 vs int64)
    detect_kernel<<<1, 32>>>((const int*)ei);

    // 1-2. LN1 (nodes, edges)
    ln_kernel<<<(N + 7) / 8, blk>>>(node_feats, ln1n_g, ln1n_b, p_hln, N);
    ln_kernel<<<(E + 7) / 8, blk>>>(edge_feats, ln1e_g, ln1e_b, p_eln, E);

    // 3. pairwise distances
    dist_kernel<<<(E + 255) / 256, blk>>>(coords, ei, p_dist, E);

    // 4. zero segment-sum accumulators
    fill0_kernel<<<(int)(((size_t)N * 128 + 255) / 256), blk>>>(p_wV, (size_t)N * 128);
    fill0_kernel<<<(int)(((size_t)N * 8 + 255) / 256), blk>>>(p_z, (size_t)N * 8);

    // 5-7. q, k, v projections -> g_qkv [N, 384]
    {
        dim3 g((N + BM - 1) / BM, 128 / BN);
        sgemm_kernel<<<g, blk>>>(p_hln, Wq, p_qkv + 0,   N, 128, 128, 384, nullptr, nullptr, 0, nullptr, nullptr, 0);
        sgemm_kernel<<<g, blk>>>(p_hln, Wk, p_qkv + 128, N, 128, 128, 384, nullptr, nullptr, 0, nullptr, nullptr, 0);
        sgemm_kernel<<<g, blk>>>(p_hln, Wv, p_qkv + 256, N, 128, 128, 384, nullptr, nullptr, 0, nullptr, nullptr, 0);
    }

    // 8. ep = [LN(e) | dist] @ We  == LN(e) @ We[0:128] + dist (x) We[128]
    {
        dim3 g((E + BM - 1) / BM, 128 / BN);
        sgemm_kernel<<<g, blk>>>(p_eln, We, p_ep, E, 128, 128, 128,
                                 nullptr, nullptr, 0, p_dist, We + 128 * 128, 0);
    }

    // 9. attention per edge (alpha in-place into g_ep; atomics into wV, z)
    attn_edge_kernel<<<(E + 7) / 8, blk>>>(p_qkv, p_ep, ei, p_wV, p_z, E);

    // 10. h_attn = wV / (z + 1e-6)  -> reuse g_hln
    hattn_kernel<<<(N * 128 + 255) / 256, blk>>>(p_wV, p_z, p_hln, N);

    // 11. h2 = node_feats + h_attn @ Wo_n + bo_n      -> out_n
    {
        dim3 g((N + BM - 1) / BM, 128 / BN);
        sgemm_kernel<<<g, blk>>>(p_hln, Wo_n, out_n, N, 128, 128, 128,
                                 bo_n, node_feats, 128, nullptr, nullptr, 0);
    }
    // 12. e2 = edge_feats + alpha @ Wo_e + bo_e       -> out_e
    {
        dim3 g((E + BM - 1) / BM, 128 / BN);
        sgemm_kernel<<<g, blk>>>(p_ep, Wo_e, out_e, E, 128, 128, 128,
                                 bo_e, edge_feats, 128, nullptr, nullptr, 0);
    }

    // 13-15. node FFN: hn = LN2(h2); h3 = silu(hn@Wn1)@Wn2; out_n = h2 + h3
    ln_kernel<<<(N + 7) / 8, blk>>>(out_n, ln2n_g, ln2n_b, p_hln, N);
    {
        dim3 g1((N + BM - 1) / BM, 256 / BN);
        sgemm_kernel<<<g1, blk>>>(p_hln, Wn1, p_t, N, 128, 256, 256,
                                  nullptr, nullptr, 0, nullptr, nullptr, 1);
        dim3 g2((N + BM - 1) / BM, 128 / BN);
        sgemm_kernel<<<g2, blk>>>(p_t, Wn2, out_n, N, 256, 128, 128,
                                  nullptr, out_n, 128, nullptr, nullptr, 0);
    }

    // 16-18. edge FFN: en = LN2(e2); e3 = silu(en@We1)@We2; out_e = e2 + e3
    ln_kernel<<<(E + 7) / 8, blk>>>(out_e, ln2e_g, ln2e_b, p_eln, E);
    {
        dim3 g1((E + BM - 1) / BM, 256 / BN);
        sgemm_kernel<<<g1, blk>>>(p_eln, We1, p_t, E, 128, 256, 256,
                                  nullptr, nullptr, 0, nullptr, nullptr, 1);
        dim3 g2((E + BM - 1) / BM, 128 / BN);
        sgemm_kernel<<<g2, blk>>>(p_t, We2, out_e, E, 256, 128, 128,
                                  nullptr, out_e, 128, nullptr, nullptr, 0);
    }
}

// round 4
// speedup vs baseline: 1.2810x; 1.2810x over previous
#include <cuda_runtime.h>
#include <math.h>
#include <stdint.h>

// ---------------------------------------------------------------------------
// GraphTransformer layer: N=50000, E=600000, C=128, H=8, Dh=16
// Round 4: GEMMs on legacy mma.sync m16n8k8 tf32 (compute_103-safe HMMA).
// ---------------------------------------------------------------------------

#define N_MAX 50000
#define E_MAX 600000

__device__ float g_hln[(size_t)N_MAX * 128];
__device__ float g_qkv[(size_t)N_MAX * 384];
__device__ float g_eln[(size_t)E_MAX * 128];
__device__ float g_ep [(size_t)E_MAX * 128];
__device__ float g_dist[(size_t)E_MAX];
__device__ float g_wV [(size_t)N_MAX * 128];
__device__ float g_z  [(size_t)N_MAX * 8];
__device__ float g_t  [(size_t)E_MAX * 256];
__device__ float g_wT [229376];                 // transposed weights
__device__ int   g_is64;

// ---------------------------------------------------------------------------
// tf32 helpers
// ---------------------------------------------------------------------------
__device__ __forceinline__ float to_tf32(float f) {
    uint32_t u;
    asm("cvt.rna.tf32.f32 %0, %1;" : "=r"(u) : "f"(f));
    return __uint_as_float(u);
}

__device__ __forceinline__ void mma_tf32(float* c, const uint32_t* a,
                                         uint32_t b0, uint32_t b1) {
    asm volatile(
        "mma.sync.aligned.m16n8k8.row.col.f32.tf32.tf32.f32 "
        "{%0,%1,%2,%3}, {%4,%5,%6,%7}, {%8,%9}, {%0,%1,%2,%3};"
        : "+f"(c[0]), "+f"(c[1]), "+f"(c[2]), "+f"(c[3])
        : "r"(a[0]), "r"(a[1]), "r"(a[2]), "r"(a[3]), "r"(b0), "r"(b1));
}

// ---------------------------------------------------------------------------
// tf32 HMMA GEMM: C[M, gridDim.y*128] = epi(A[M,K] @ W) with W given
// transposed as BT[Nw,K]. Block tile 128x128, BK=32, 8 warps (4x2).
// Epilogue: +bias, +r1m[m]*r1n[n], SiLU, +resid.
// ---------------------------------------------------------------------------
#define SK 36   // smem row stride (floats): conflict-free fragment loads

__global__ void __launch_bounds__(256, 2) mma_gemm(
    const float* __restrict__ A, int lda,
    const float* __restrict__ BT,
    float* __restrict__ Cout,
    int M, int K, int ldc,
    const float* __restrict__ bias,
    const float* __restrict__ resid, int ldr,
    const float* __restrict__ r1m, const float* __restrict__ r1n,
    int act)
{
    __shared__ float sA[128][SK];
    __shared__ float sB[128][SK];

    const int tid = threadIdx.x;
    const int wid = tid >> 5;
    const int lane = tid & 31;
    const int warp_m = wid & 3;     // 4 warps over M (32 rows each)
    const int warp_n = wid >> 2;    // 2 warps over N (64 cols each)
    const int m0 = blockIdx.x * 128;
    const int n0 = blockIdx.y * 128;

    const int grp = lane >> 2;      // 0..7
    const int tig = lane & 3;       // 0..3

    float acc[2][8][4];
    #pragma unroll
    for (int t = 0; t < 2; t++)
        #pragma unroll
        for (int j = 0; j < 8; j++)
            #pragma unroll
            for (int c = 0; c < 4; c++) acc[t][j][c] = 0.0f;

    const int lr = tid >> 1;          // row 0..127
    const int lc = (tid & 1) * 16;    // col 0 or 16

    for (int k0 = 0; k0 < K; k0 += 32) {
        // A tile [128, 32] -> tf32 in smem (rows >= M zero-padded)
        {
            const bool ok = (m0 + lr) < M;
            const float* src = A + (size_t)(m0 + lr) * lda + k0 + lc;
            #pragma unroll
            for (int q = 0; q < 4; q++) {
                float4 v = ok ? *(const float4*)(src + q * 4)
                              : make_float4(0.f, 0.f, 0.f, 0.f);
                sA[lr][lc + q * 4 + 0] = to_tf32(v.x);
                sA[lr][lc + q * 4 + 1] = to_tf32(v.y);
                sA[lr][lc + q * 4 + 2] = to_tf32(v.z);
                sA[lr][lc + q * 4 + 3] = to_tf32(v.w);
            }
        }
        // B tile [128 n-rows, 32 k] from BT[Nw,K]
        {
            const float* src = BT + (size_t)(n0 + lr) * K + k0 + lc;
            #pragma unroll
            for (int q = 0; q < 4; q++) {
                float4 v = *(const float4*)(src + q * 4);
                sB[lr][lc + q * 4 + 0] = to_tf32(v.x);
                sB[lr][lc + q * 4 + 1] = to_tf32(v.y);
                sB[lr][lc + q * 4 + 2] = to_tf32(v.z);
                sB[lr][lc + q * 4 + 3] = to_tf32(v.w);
            }
        }
        __syncthreads();

        #pragma unroll
        for (int ks = 0; ks < 4; ks++) {
            const int kk = ks * 8;
            uint32_t a[2][4];
            #pragma unroll
            for (int t = 0; t < 2; t++) {
                const int mr = warp_m * 32 + t * 16 + grp;
                a[t][0] = __float_as_uint(sA[mr][kk + tig]);
                a[t][1] = __float_as_uint(sA[mr + 8][kk + tig]);
                a[t][2] = __float_as_uint(sA[mr][kk + tig + 4]);
                a[t][3] = __float_as_uint(sA[mr + 8][kk + tig + 4]);
            }
            #pragma unroll
            for (int j = 0; j < 8; j++) {
                const int nr = warp_n * 64 + j * 8 + grp;
                const uint32_t b0 = __float_as_uint(sB[nr][kk + tig]);
                const uint32_t b1 = __float_as_uint(sB[nr][kk + tig + 4]);
                mma_tf32(acc[0][j], a[0], b0, b1);
                mma_tf32(acc[1][j], a[1], b0, b1);
            }
        }
        __syncthreads();
    }

    // epilogue
    #pragma unroll
    for (int t = 0; t < 2; t++) {
        #pragma unroll
        for (int half = 0; half < 2; half++) {
            const int m = m0 + warp_m * 32 + t * 16 + grp + half * 8;
            if (m >= M) continue;
            const float r1 = r1m ? r1m[m] : 0.0f;
            float* orow = Cout + (size_t)m * ldc;
            const float* rrow = resid ? resid + (size_t)m * ldr : nullptr;
            #pragma unroll
            for (int j = 0; j < 8; j++) {
                const int col = n0 + warp_n * 64 + j * 8 + tig * 2;
                float v0 = acc[t][j][half * 2 + 0];
                float v1 = acc[t][j][half * 2 + 1];
                if (bias) { v0 += bias[col]; v1 += bias[col + 1]; }
                if (r1m)  { v0 += r1 * r1n[col]; v1 += r1 * r1n[col + 1]; }
                if (act) {
                    v0 = v0 / (1.0f + expf(-v0));
                    v1 = v1 / (1.0f + expf(-v1));
                }
                if (resid) { v0 += rrow[col]; v1 += rrow[col + 1]; }
                float2 o2; o2.x = v0; o2.y = v1;
                *(float2*)(orow + col) = o2;
            }
        }
    }
}

// ---------------------------------------------------------------------------
// Weight transpose: src[R,C] -> dst[C,R]
// ---------------------------------------------------------------------------
__global__ void transpose_kernel(const float* __restrict__ src,
                                 float* __restrict__ dst, int R, int Cc)
{
    __shared__ float tile[32][33];
    int c0 = blockIdx.x * 32, r0 = blockIdx.y * 32;
    int tx = threadIdx.x, ty = threadIdx.y;
    for (int dy = 0; dy < 32; dy += 8) {
        int r = r0 + ty + dy, c = c0 + tx;
        if (r < R && c < Cc) tile[ty + dy][tx] = src[(size_t)r * Cc + c];
    }
    __syncthreads();
    for (int dy = 0; dy < 32; dy += 8) {
        int c = c0 + ty + dy, r = r0 + tx;
        if (r < R && c < Cc) dst[(size_t)c * R + r] = tile[tx][ty + dy];
    }
}

// ---------------------------------------------------------------------------
// misc kernels
// ---------------------------------------------------------------------------
__global__ void detect_kernel(const int* __restrict__ ei32)
{
    if (threadIdx.x == 0 && blockIdx.x == 0) {
        int any = 0;
        #pragma unroll 8
        for (int i = 0; i < 64; i++) any |= ei32[2 * i + 1];
        g_is64 = (any == 0) ? 1 : 0;
    }
}
__device__ __forceinline__ int edge_idx(const void* __restrict__ ei, long long pos)
{
    if (g_is64) return (int)((const long long*)ei)[pos];
    return ((const int*)ei)[pos];
}

__global__ void ln_kernel(const float* __restrict__ x,
                          const float* __restrict__ g,
                          const float* __restrict__ b,
                          float* __restrict__ out, int M)
{
    int w = (blockIdx.x * blockDim.x + threadIdx.x) >> 5;
    int lane = threadIdx.x & 31;
    if (w >= M) return;
    float4 v = *(const float4*)(x + (size_t)w * 128 + lane * 4);
    float s  = v.x + v.y + v.z + v.w;
    float sq = v.x*v.x + v.y*v.y + v.z*v.z + v.w*v.w;
    #pragma unroll
    for (int o = 16; o; o >>= 1) {
        s  += __shfl_xor_sync(0xffffffffu, s,  o);
        sq += __shfl_xor_sync(0xffffffffu, sq, o);
    }
    float mu  = s * (1.0f / 128.0f);
    float var = sq * (1.0f / 128.0f) - mu * mu;
    float rs  = rsqrtf(var + 1e-5f);
    float4 gv = *(const float4*)(g + lane * 4);
    float4 bv = *(const float4*)(b + lane * 4);
    float4 o4;
    o4.x = (v.x - mu) * rs * gv.x + bv.x;
    o4.y = (v.y - mu) * rs * gv.y + bv.y;
    o4.z = (v.z - mu) * rs * gv.z + bv.z;
    o4.w = (v.w - mu) * rs * gv.w + bv.w;
    *(float4*)(out + (size_t)w * 128 + lane * 4) = o4;
}

__global__ void dist_kernel(const float* __restrict__ coords,
                            const void* __restrict__ ei,
                            float* __restrict__ dist, int E)
{
    int e = blockIdx.x * blockDim.x + threadIdx.x;
    if (e >= E) return;
    int r = edge_idx(ei, e);
    int c = edge_idx(ei, (long long)E + e);
    float dx = coords[r * 3 + 0] - coords[c * 3 + 0];
    float dy = coords[r * 3 + 1] - coords[c * 3 + 1];
    float dz = coords[r * 3 + 2] - coords[c * 3 + 2];
    dist[e] = 0.1f * sqrtf(dx * dx + dy * dy + dz * dz);
}

__global__ void fill0_kernel(float* __restrict__ p, size_t n)
{
    size_t i = (size_t)blockIdx.x * blockDim.x + threadIdx.x;
    if (i < n) p[i] = 0.0f;
}

__global__ void attn_edge_kernel(const float* __restrict__ qkv,
                                 float* __restrict__ ep_alpha,
                                 const void* __restrict__ ei,
                                 float* __restrict__ wV,
                                 float* __restrict__ z,
                                 int E)
{
    int w = (blockIdx.x * blockDim.x + threadIdx.x) >> 5;
    int lane = threadIdx.x & 31;
    if (w >= E) return;
    int r = edge_idx(ei, w);
    int c = edge_idx(ei, (long long)E + w);

    float4 q4 = *(const float4*)(qkv + (size_t)c * 384 + lane * 4);
    float4 k4 = *(const float4*)(qkv + (size_t)r * 384 + 128 + lane * 4);
    float4 v4 = *(const float4*)(qkv + (size_t)r * 384 + 256 + lane * 4);
    float4 e4 = *(const float4*)(ep_alpha + (size_t)w * 128 + lane * 4);

    float4 a4;
    a4.x = fminf(fmaxf(k4.x * q4.x * 0.25f, -5.0f), 5.0f) * e4.x;
    a4.y = fminf(fmaxf(k4.y * q4.y * 0.25f, -5.0f), 5.0f) * e4.y;
    a4.z = fminf(fmaxf(k4.z * q4.z * 0.25f, -5.0f), 5.0f) * e4.z;
    a4.w = fminf(fmaxf(k4.w * q4.w * 0.25f, -5.0f), 5.0f) * e4.w;
    *(float4*)(ep_alpha + (size_t)w * 128 + lane * 4) = a4;

    float hs = a4.x + a4.y + a4.z + a4.w;
    hs += __shfl_xor_sync(0xffffffffu, hs, 1);
    hs += __shfl_xor_sync(0xffffffffu, hs, 2);
    float ax = expf(fminf(fmaxf(hs, -5.0f), 5.0f));

    float* wvp = wV + (size_t)c * 128 + lane * 4;
    atomicAdd(wvp + 0, v4.x * ax);
    atomicAdd(wvp + 1, v4.y * ax);
    atomicAdd(wvp + 2, v4.z * ax);
    atomicAdd(wvp + 3, v4.w * ax);
    if ((lane & 3) == 0)
        atomicAdd(z + (size_t)c * 8 + (lane >> 2), ax);
}

__global__ void hattn_kernel(const float* __restrict__ wV,
                             const float* __restrict__ z,
                             float* __restrict__ out, int N)
{
    int i = blockIdx.x * blockDim.x + threadIdx.x;
    if (i >= N * 128) return;
    int n = i >> 7;
    int h = (i & 127) >> 4;
    out[i] = wV[i] / (z[(size_t)n * 8 + h] + 1e-6f);
}

// ---------------------------------------------------------------------------
// Launch
// ---------------------------------------------------------------------------
extern "C" void kernel_launch(void* const* d_in, const int* in_sizes, int n_in,
                              void* d_out, int out_size)
{
    const float* node_feats = (const float*)d_in[0];
    const float* edge_feats = (const float*)d_in[1];
    const float* coords     = (const float*)d_in[2];
    const void*  ei         = d_in[3];
    const float* Wq   = (const float*)d_in[4];
    const float* Wk   = (const float*)d_in[5];
    const float* Wv   = (const float*)d_in[6];
    const float* We   = (const float*)d_in[7];
    const float* Wo_n = (const float*)d_in[8];
    const float* bo_n = (const float*)d_in[9];
    const float* Wo_e = (const float*)d_in[10];
    const float* bo_e = (const float*)d_in[11];
    const float* ln1n_g = (const float*)d_in[12];
    const float* ln1n_b = (const float*)d_in[13];
    const float* ln1e_g = (const float*)d_in[14];
    const float* ln1e_b = (const float*)d_in[15];
    const float* ln2n_g = (const float*)d_in[16];
    const float* ln2n_b = (const float*)d_in[17];
    const float* ln2e_g = (const float*)d_in[18];
    const float* ln2e_b = (const float*)d_in[19];
    const float* Wn1 = (const float*)d_in[20];
    const float* Wn2 = (const float*)d_in[21];
    const float* We1 = (const float*)d_in[22];
    const float* We2 = (const float*)d_in[23];

    int N = in_sizes[0] / 128;
    int E = in_sizes[1] / 128;

    float* out   = (float*)d_out;
    float* out_n = out;
    float* out_e = out + (size_t)N * 128;

    float *p_hln, *p_qkv, *p_eln, *p_ep, *p_dist, *p_wV, *p_z, *p_t, *p_wT;
    cudaGetSymbolAddress((void**)&p_hln,  g_hln);
    cudaGetSymbolAddress((void**)&p_qkv,  g_qkv);
    cudaGetSymbolAddress((void**)&p_eln,  g_eln);
    cudaGetSymbolAddress((void**)&p_ep,   g_ep);
    cudaGetSymbolAddress((void**)&p_dist, g_dist);
    cudaGetSymbolAddress((void**)&p_wV,   g_wV);
    cudaGetSymbolAddress((void**)&p_z,    g_z);
    cudaGetSymbolAddress((void**)&p_t,    g_t);
    cudaGetSymbolAddress((void**)&p_wT,   g_wT);

    // transposed weight layout
    float* WqkvT = p_wT + 0;        // [384,128]: WqT | WkT | WvT
    float* WeT   = p_wT + 49152;    // [128,128]
    float* WonT  = p_wT + 65536;    // [128,128]
    float* WoeT  = p_wT + 81920;    // [128,128]
    float* Wn1T  = p_wT + 98304;    // [256,128]
    float* Wn2T  = p_wT + 131072;   // [128,256]
    float* We1T  = p_wT + 163840;   // [256,128]
    float* We2T  = p_wT + 196608;   // [128,256]

    dim3 blk(256);
    dim3 tblk(32, 8);

    detect_kernel<<<1, 32>>>((const int*)ei);

    {
        dim3 g44(4, 4), g84(8, 4), g48(4, 8);
        transpose_kernel<<<g44, tblk>>>(Wq,   WqkvT + 0,     128, 128);
        transpose_kernel<<<g44, tblk>>>(Wk,   WqkvT + 16384, 128, 128);
        transpose_kernel<<<g44, tblk>>>(Wv,   WqkvT + 32768, 128, 128);
        transpose_kernel<<<g44, tblk>>>(We,   WeT, 128, 128);   // first 128 rows
        transpose_kernel<<<g44, tblk>>>(Wo_n, WonT, 128, 128);
        transpose_kernel<<<g44, tblk>>>(Wo_e, WoeT, 128, 128);
        transpose_kernel<<<g84, tblk>>>(Wn1,  Wn1T, 128, 256);
        transpose_kernel<<<g48, tblk>>>(Wn2,  Wn2T, 256, 128);
        transpose_kernel<<<g84, tblk>>>(We1,  We1T, 128, 256);
        transpose_kernel<<<g48, tblk>>>(We2,  We2T, 256, 128);
    }

    ln_kernel<<<(N + 7) / 8, blk>>>(node_feats, ln1n_g, ln1n_b, p_hln, N);
    ln_kernel<<<(E + 7) / 8, blk>>>(edge_feats, ln1e_g, ln1e_b, p_eln, E);
    dist_kernel<<<(E + 255) / 256, blk>>>(coords, ei, p_dist, E);
    fill0_kernel<<<(int)(((size_t)N * 128 + 255) / 256), blk>>>(p_wV, (size_t)N * 128);
    fill0_kernel<<<(int)(((size_t)N * 8 + 255) / 256), blk>>>(p_z, (size_t)N * 8);

    const int gN = (N + 127) / 128;
    const int gE = (E + 127) / 128;

    // qkv fused: [N,128] @ [128,384]
    mma_gemm<<<dim3(gN, 3), blk>>>(p_hln, 128, WqkvT, p_qkv, N, 128, 384,
                                   nullptr, nullptr, 0, nullptr, nullptr, 0);

    // ep = LN(e) @ We[0:128] + dist (x) We[128]
    mma_gemm<<<dim3(gE, 1), blk>>>(p_eln, 128, WeT, p_ep, E, 128, 128,
                                   nullptr, nullptr, 0, p_dist, We + 128 * 128, 0);

    attn_edge_kernel<<<(E + 7) / 8, blk>>>(p_qkv, p_ep, ei, p_wV, p_z, E);
    hattn_kernel<<<(N * 128 + 255) / 256, blk>>>(p_wV, p_z, p_hln, N);

    // h2, e2 (residual + bias)
    mma_gemm<<<dim3(gN, 1), blk>>>(p_hln, 128, WonT, out_n, N, 128, 128,
                                   bo_n, node_feats, 128, nullptr, nullptr, 0);
    mma_gemm<<<dim3(gE, 1), blk>>>(p_ep, 128, WoeT, out_e, E, 128, 128,
                                   bo_e, edge_feats, 128, nullptr, nullptr, 0);

    // node FFN
    ln_kernel<<<(N + 7) / 8, blk>>>(out_n, ln2n_g, ln2n_b, p_hln, N);
    mma_gemm<<<dim3(gN, 2), blk>>>(p_hln, 128, Wn1T, p_t, N, 128, 256,
                                   nullptr, nullptr, 0, nullptr, nullptr, 1);
    mma_gemm<<<dim3(gN, 1), blk>>>(p_t, 256, Wn2T, out_n, N, 256, 128,
                                   nullptr, out_n, 128, nullptr, nullptr, 0);

    // edge FFN
    ln_kernel<<<(E + 7) / 8, blk>>>(out_e, ln2e_g, ln2e_b, p_eln, E);
    mma_gemm<<<dim3(gE, 2), blk>>>(p_eln, 128, We1T, p_t, E, 128, 256,
                                   nullptr, nullptr, 0, nullptr, nullptr, 1);
    mma_gemm<<<dim3(gE, 1), blk>>>(p_t, 256, We2T, out_e, E, 256, 128,
                                   nullptr, out_e, 128, nullptr, nullptr, 0);
}

// round 5
// speedup vs baseline: 2.7631x; 2.1569x over previous
#include <cuda_runtime.h>
#include <cuda_fp16.h>
#include <math.h>
#include <stdint.h>

// ---------------------------------------------------------------------------
// GraphTransformer layer: N=50000, E=600000, C=128, H=8, Dh=16
// Round 5: fp16 HMMA m16n8k16 + cp.async double-buffered GEMM; half storage
// for GEMM-only tensors (LN outs, qkv, FFN hidden, weights).
// ---------------------------------------------------------------------------

#define N_MAX 50000
#define E_MAX 600000

__device__ __half g_hln[(size_t)N_MAX * 128];   // ln1n / h_attn / ln2n (half)
__device__ __half g_qkv[(size_t)N_MAX * 384];   // q|k|v (half)
__device__ __half g_eln[(size_t)E_MAX * 128];   // ln1e / ln2e (half)
__device__ float  g_ep [(size_t)E_MAX * 128];   // ep then alpha (fp32, in-place)
__device__ float  g_dist[(size_t)E_MAX];
__device__ float  g_wV [(size_t)N_MAX * 128];
__device__ float  g_z  [(size_t)N_MAX * 8];
__device__ __half g_t  [(size_t)E_MAX * 256];   // FFN hidden (half)
__device__ __half g_wT [229376];                // transposed half weights
__device__ int    g_is64;

// ---------------------------------------------------------------------------
// MMA + cp.async primitives (sm_80-compatible PTX, safe at compute_103)
// ---------------------------------------------------------------------------
__device__ __forceinline__ void mma_f16(float* c, const uint32_t* a,
                                        uint32_t b0, uint32_t b1) {
    asm volatile(
        "mma.sync.aligned.m16n8k16.row.col.f32.f16.f16.f32 "
        "{%0,%1,%2,%3}, {%4,%5,%6,%7}, {%8,%9}, {%0,%1,%2,%3};"
        : "+f"(c[0]), "+f"(c[1]), "+f"(c[2]), "+f"(c[3])
        : "r"(a[0]), "r"(a[1]), "r"(a[2]), "r"(a[3]), "r"(b0), "r"(b1));
}
#define CP16(d, s, n) asm volatile("cp.async.cg.shared.global [%0], [%1], 16, %2;" :: "r"(d), "l"(s), "r"(n) : "memory")
#define CPCOMMIT()    asm volatile("cp.async.commit_group;" ::: "memory")
#define CPWAIT(n)     asm volatile("cp.async.wait_group %0;" :: "n"(n) : "memory")

#define SKH 40                    // halfs per smem row (32 data + 8 pad)
#define BUFB (128 * SKH * 2)      // bytes per tile buffer

// ---------------------------------------------------------------------------
// fp16 HMMA GEMM: C[M, ...] = epi(A[M,K] @ W), W transposed as BT[Nw,K] half.
// CTA tile 128x128, BK=32, 8 warps (4x2), warp tile 32x64, double-buffered.
// AHALF: A is half in gmem (cp.async); else fp32 (reg prefetch + cvt + STS).
// ---------------------------------------------------------------------------
template<bool AHALF>
__global__ void __launch_bounds__(256, 2) mma_gemm(
    const void* __restrict__ Ap, int lda,
    const __half* __restrict__ BT,
    float* __restrict__ Cf, __half* __restrict__ Ch,
    int M, int K, int ldc,
    const float* __restrict__ bias,
    const float* __restrict__ resid, int ldr,
    const float* __restrict__ r1m, const float* __restrict__ r1n,
    int act)
{
    __shared__ __half sA[2][128 * SKH];
    __shared__ __half sB[2][128 * SKH];

    const int tid = threadIdx.x;
    const int wid = tid >> 5;
    const int lane = tid & 31;
    const int warp_m = wid & 3;
    const int warp_n = wid >> 2;
    const int m0 = blockIdx.x * 128;
    const int n0 = blockIdx.y * 128;
    const int grp = lane >> 2;
    const int tig = lane & 3;

    const uint32_t sA0 = (uint32_t)__cvta_generic_to_shared(&sA[0][0]);
    const uint32_t sB0 = (uint32_t)__cvta_generic_to_shared(&sB[0][0]);

    // per-thread load coordinates
    const int arow = tid >> 2, aj = tid & 3;       // half path: 2 granules (rows arow, arow+64)
    const int frow = tid >> 3, fj = tid & 7;       // fp32 path: 4 quads (rows frow, +32, +64, +96)

    float acc[2][8][4];
    #pragma unroll
    for (int t = 0; t < 2; t++)
        #pragma unroll
        for (int j = 0; j < 8; j++)
            #pragma unroll
            for (int c = 0; c < 4; c++) acc[t][j][c] = 0.0f;

    const int nc = K >> 5;
    float4 ar[4];   // fp32-A prefetch regs

    // ---- loaders ----
    auto loadB = [&](int c, int buf) {
        const int k0 = c << 5;
        #pragma unroll
        for (int i = 0; i < 2; i++) {
            const int row = arow + i * 64;
            const uint32_t dst = sB0 + buf * BUFB + row * (SKH * 2) + aj * 16;
            const __half* src = BT + (size_t)(n0 + row) * K + k0 + aj * 8;
            CP16(dst, src, 16);
        }
    };
    auto loadA_half = [&](int c, int buf) {
        const __half* Ah = (const __half*)Ap;
        const int k0 = c << 5;
        #pragma unroll
        for (int i = 0; i < 2; i++) {
            const int row = arow + i * 64;
            const uint32_t dst = sA0 + buf * BUFB + row * (SKH * 2) + aj * 16;
            const int ok = (m0 + row) < M;
            const __half* src = Ah + (size_t)(ok ? (m0 + row) : 0) * lda + k0 + aj * 8;
            CP16(dst, src, ok ? 16 : 0);
        }
    };
    auto loadA_f32_regs = [&](int c) {
        const float* Af = (const float*)Ap;
        const int k0 = c << 5;
        #pragma unroll
        for (int i = 0; i < 4; i++) {
            const int row = frow + i * 32;
            ar[i] = (m0 + row < M)
                  ? *(const float4*)(Af + (size_t)(m0 + row) * lda + k0 + fj * 4)
                  : make_float4(0.f, 0.f, 0.f, 0.f);
        }
    };
    auto stsA_f32 = [&](int buf) {
        #pragma unroll
        for (int i = 0; i < 4; i++) {
            const int row = frow + i * 32;
            __half2 h0 = __floats2half2_rn(ar[i].x, ar[i].y);
            __half2 h1 = __floats2half2_rn(ar[i].z, ar[i].w);
            uint2 u; u.x = *(uint32_t*)&h0; u.y = *(uint32_t*)&h1;
            *(uint2*)(&sA[buf][row * SKH + fj * 4]) = u;
        }
    };

    // ---- compute one buffered chunk ----
    auto compute = [&](int buf) {
        const __half* Ab = &sA[buf][0];
        const __half* Bb = &sB[buf][0];
        #pragma unroll
        for (int ks = 0; ks < 2; ks++) {
            const int kk = ks * 16;
            uint32_t a[2][4];
            #pragma unroll
            for (int t = 0; t < 2; t++) {
                const __half* ap = Ab + (warp_m * 32 + t * 16 + grp) * SKH + kk + 2 * tig;
                a[t][0] = *(const uint32_t*)(ap);
                a[t][1] = *(const uint32_t*)(ap + 8 * SKH);
                a[t][2] = *(const uint32_t*)(ap + 8);
                a[t][3] = *(const uint32_t*)(ap + 8 * SKH + 8);
            }
            #pragma unroll
            for (int j = 0; j < 8; j++) {
                const __half* bp = Bb + (warp_n * 64 + j * 8 + grp) * SKH + kk + 2 * tig;
                const uint32_t b0 = *(const uint32_t*)(bp);
                const uint32_t b1 = *(const uint32_t*)(bp + 8);
                mma_f16(acc[0][j], a[0], b0, b1);
                mma_f16(acc[1][j], a[1], b0, b1);
            }
        }
    };

    // ---- pipelined main loop ----
    if (AHALF) {
        loadA_half(0, 0); loadB(0, 0); CPCOMMIT();
        for (int c = 0; c < nc; c++) {
            if (c + 1 < nc) {
                loadA_half(c + 1, (c + 1) & 1); loadB(c + 1, (c + 1) & 1);
                CPCOMMIT(); CPWAIT(1);
            } else CPWAIT(0);
            __syncthreads();
            compute(c & 1);
            __syncthreads();
        }
    } else {
        loadA_f32_regs(0);
        loadB(0, 0); CPCOMMIT();
        for (int c = 0; c < nc; c++) {
            stsA_f32(c & 1);
            if (c + 1 < nc) {
                loadB(c + 1, (c + 1) & 1); CPCOMMIT();
                loadA_f32_regs(c + 1);
                CPWAIT(1);
            } else CPWAIT(0);
            __syncthreads();
            compute(c & 1);
            __syncthreads();
        }
    }

    // ---- epilogue ----
    #pragma unroll
    for (int t = 0; t < 2; t++) {
        #pragma unroll
        for (int half = 0; half < 2; half++) {
            const int m = m0 + warp_m * 32 + t * 16 + grp + half * 8;
            if (m >= M) continue;
            const float r1 = r1m ? r1m[m] : 0.0f;
            const float* rrow = resid ? resid + (size_t)m * ldr : nullptr;
            #pragma unroll
            for (int j = 0; j < 8; j++) {
                const int col = n0 + warp_n * 64 + j * 8 + tig * 2;
                float v0 = acc[t][j][half * 2 + 0];
                float v1 = acc[t][j][half * 2 + 1];
                if (bias) { v0 += bias[col]; v1 += bias[col + 1]; }
                if (r1m)  { v0 += r1 * r1n[col]; v1 += r1 * r1n[col + 1]; }
                if (act) {
                    v0 = v0 / (1.0f + expf(-v0));
                    v1 = v1 / (1.0f + expf(-v1));
                }
                if (resid) { v0 += rrow[col]; v1 += rrow[col + 1]; }
                if (Ch) {
                    *(__half2*)(Ch + (size_t)m * ldc + col) = __floats2half2_rn(v0, v1);
                } else {
                    float2 o2; o2.x = v0; o2.y = v1;
                    *(float2*)(Cf + (size_t)m * ldc + col) = o2;
                }
            }
        }
    }
}

// ---------------------------------------------------------------------------
// Weight transpose to half: src[R,C] fp32 -> dst[C,R] half
// ---------------------------------------------------------------------------
__global__ void transpose_kernel(const float* __restrict__ src,
                                 __half* __restrict__ dst, int R, int Cc)
{
    __shared__ float tile[32][33];
    int c0 = blockIdx.x * 32, r0 = blockIdx.y * 32;
    int tx = threadIdx.x, ty = threadIdx.y;
    for (int dy = 0; dy < 32; dy += 8) {
        int r = r0 + ty + dy, c = c0 + tx;
        if (r < R && c < Cc) tile[ty + dy][tx] = src[(size_t)r * Cc + c];
    }
    __syncthreads();
    for (int dy = 0; dy < 32; dy += 8) {
        int c = c0 + ty + dy, r = r0 + tx;
        if (r < R && c < Cc) dst[(size_t)c * R + r] = __float2half_rn(tile[tx][ty + dy]);
    }
}

// ---------------------------------------------------------------------------
// misc kernels
// ---------------------------------------------------------------------------
__global__ void detect_kernel(const int* __restrict__ ei32)
{
    if (threadIdx.x == 0 && blockIdx.x == 0) {
        int any = 0;
        #pragma unroll 8
        for (int i = 0; i < 64; i++) any |= ei32[2 * i + 1];
        g_is64 = (any == 0) ? 1 : 0;
    }
}
__device__ __forceinline__ int edge_idx(const void* __restrict__ ei, long long pos)
{
    if (g_is64) return (int)((const long long*)ei)[pos];
    return ((const int*)ei)[pos];
}

// LayerNorm: one warp per row, half output
__global__ void ln_kernel(const float* __restrict__ x,
                          const float* __restrict__ g,
                          const float* __restrict__ b,
                          __half* __restrict__ out, int M)
{
    int w = (blockIdx.x * blockDim.x + threadIdx.x) >> 5;
    int lane = threadIdx.x & 31;
    if (w >= M) return;
    float4 v = *(const float4*)(x + (size_t)w * 128 + lane * 4);
    float s  = v.x + v.y + v.z + v.w;
    float sq = v.x*v.x + v.y*v.y + v.z*v.z + v.w*v.w;
    #pragma unroll
    for (int o = 16; o; o >>= 1) {
        s  += __shfl_xor_sync(0xffffffffu, s,  o);
        sq += __shfl_xor_sync(0xffffffffu, sq, o);
    }
    float mu  = s * (1.0f / 128.0f);
    float var = sq * (1.0f / 128.0f) - mu * mu;
    float rs  = rsqrtf(var + 1e-5f);
    float4 gv = *(const float4*)(g + lane * 4);
    float4 bv = *(const float4*)(b + lane * 4);
    __half2 h0 = __floats2half2_rn((v.x - mu) * rs * gv.x + bv.x,
                                   (v.y - mu) * rs * gv.y + bv.y);
    __half2 h1 = __floats2half2_rn((v.z - mu) * rs * gv.z + bv.z,
                                   (v.w - mu) * rs * gv.w + bv.w);
    uint2 u; u.x = *(uint32_t*)&h0; u.y = *(uint32_t*)&h1;
    *(uint2*)(out + (size_t)w * 128 + lane * 4) = u;
}

__global__ void dist_kernel(const float* __restrict__ coords,
                            const void* __restrict__ ei,
                            float* __restrict__ dist, int E)
{
    int e = blockIdx.x * blockDim.x + threadIdx.x;
    if (e >= E) return;
    int r = edge_idx(ei, e);
    int c = edge_idx(ei, (long long)E + e);
    float dx = coords[r * 3 + 0] - coords[c * 3 + 0];
    float dy = coords[r * 3 + 1] - coords[c * 3 + 1];
    float dz = coords[r * 3 + 2] - coords[c * 3 + 2];
    dist[e] = 0.1f * sqrtf(dx * dx + dy * dy + dz * dz);
}

__global__ void fill0_kernel(float* __restrict__ p, size_t n)
{
    size_t i = (size_t)blockIdx.x * blockDim.x + threadIdx.x;
    if (i < n) p[i] = 0.0f;
}

__device__ __forceinline__ float4 ld_half4(const __half* p)
{
    uint2 u = *(const uint2*)p;
    __half2 h0 = *(__half2*)&u.x, h1 = *(__half2*)&u.y;
    float2 f0 = __half22float2(h0), f1 = __half22float2(h1);
    return make_float4(f0.x, f0.y, f1.x, f1.y);
}

// edge attention: one warp per edge (qkv half, ep/alpha fp32)
__global__ void attn_edge_kernel(const __half* __restrict__ qkv,
                                 float* __restrict__ ep_alpha,
                                 const void* __restrict__ ei,
                                 float* __restrict__ wV,
                                 float* __restrict__ z,
                                 int E)
{
    int w = (blockIdx.x * blockDim.x + threadIdx.x) >> 5;
    int lane = threadIdx.x & 31;
    if (w >= E) return;
    int r = edge_idx(ei, w);
    int c = edge_idx(ei, (long long)E + w);

    float4 q4 = ld_half4(qkv + (size_t)c * 384 + lane * 4);
    float4 k4 = ld_half4(qkv + (size_t)r * 384 + 128 + lane * 4);
    float4 v4 = ld_half4(qkv + (size_t)r * 384 + 256 + lane * 4);
    float4 e4 = *(const float4*)(ep_alpha + (size_t)w * 128 + lane * 4);

    float4 a4;
    a4.x = fminf(fmaxf(k4.x * q4.x * 0.25f, -5.0f), 5.0f) * e4.x;
    a4.y = fminf(fmaxf(k4.y * q4.y * 0.25f, -5.0f), 5.0f) * e4.y;
    a4.z = fminf(fmaxf(k4.z * q4.z * 0.25f, -5.0f), 5.0f) * e4.z;
    a4.w = fminf(fmaxf(k4.w * q4.w * 0.25f, -5.0f), 5.0f) * e4.w;
    *(float4*)(ep_alpha + (size_t)w * 128 + lane * 4) = a4;

    float hs = a4.x + a4.y + a4.z + a4.w;
    hs += __shfl_xor_sync(0xffffffffu, hs, 1);
    hs += __shfl_xor_sync(0xffffffffu, hs, 2);
    float ax = expf(fminf(fmaxf(hs, -5.0f), 5.0f));

    float* wvp = wV + (size_t)c * 128 + lane * 4;
    atomicAdd(wvp + 0, v4.x * ax);
    atomicAdd(wvp + 1, v4.y * ax);
    atomicAdd(wvp + 2, v4.z * ax);
    atomicAdd(wvp + 3, v4.w * ax);
    if ((lane & 3) == 0)
        atomicAdd(z + (size_t)c * 8 + (lane >> 2), ax);
}

__global__ void hattn_kernel(const float* __restrict__ wV,
                             const float* __restrict__ z,
                             __half* __restrict__ out, int N)
{
    int i = blockIdx.x * blockDim.x + threadIdx.x;
    if (i >= N * 128) return;
    int n = i >> 7;
    int h = (i & 127) >> 4;
    out[i] = __float2half_rn(wV[i] / (z[(size_t)n * 8 + h] + 1e-6f));
}

// ---------------------------------------------------------------------------
// Launch
// ---------------------------------------------------------------------------
extern "C" void kernel_launch(void* const* d_in, const int* in_sizes, int n_in,
                              void* d_out, int out_size)
{
    const float* node_feats = (const float*)d_in[0];
    const float* edge_feats = (const float*)d_in[1];
    const float* coords     = (const float*)d_in[2];
    const void*  ei         = d_in[3];
    const float* Wq   = (const float*)d_in[4];
    const float* Wk   = (const float*)d_in[5];
    const float* Wv   = (const float*)d_in[6];
    const float* We   = (const float*)d_in[7];
    const float* Wo_n = (const float*)d_in[8];
    const float* bo_n = (const float*)d_in[9];
    const float* Wo_e = (const float*)d_in[10];
    const float* bo_e = (const float*)d_in[11];
    const float* ln1n_g = (const float*)d_in[12];
    const float* ln1n_b = (const float*)d_in[13];
    const float* ln1e_g = (const float*)d_in[14];
    const float* ln1e_b = (const float*)d_in[15];
    const float* ln2n_g = (const float*)d_in[16];
    const float* ln2n_b = (const float*)d_in[17];
    const float* ln2e_g = (const float*)d_in[18];
    const float* ln2e_b = (const float*)d_in[19];
    const float* Wn1 = (const float*)d_in[20];
    const float* Wn2 = (const float*)d_in[21];
    const float* We1 = (const float*)d_in[22];
    const float* We2 = (const float*)d_in[23];

    int N = in_sizes[0] / 128;
    int E = in_sizes[1] / 128;

    float* out   = (float*)d_out;
    float* out_n = out;
    float* out_e = out + (size_t)N * 128;

    __half *p_hln, *p_qkv, *p_eln, *p_t, *p_wT;
    float *p_ep, *p_dist, *p_wV, *p_z;
    cudaGetSymbolAddress((void**)&p_hln,  g_hln);
    cudaGetSymbolAddress((void**)&p_qkv,  g_qkv);
    cudaGetSymbolAddress((void**)&p_eln,  g_eln);
    cudaGetSymbolAddress((void**)&p_ep,   g_ep);
    cudaGetSymbolAddress((void**)&p_dist, g_dist);
    cudaGetSymbolAddress((void**)&p_wV,   g_wV);
    cudaGetSymbolAddress((void**)&p_z,    g_z);
    cudaGetSymbolAddress((void**)&p_t,    g_t);
    cudaGetSymbolAddress((void**)&p_wT,   g_wT);

    // transposed half weight layout
    __half* WqkvT = p_wT + 0;        // [384,128]
    __half* WeT   = p_wT + 49152;    // [128,128]
    __half* WonT  = p_wT + 65536;
    __half* WoeT  = p_wT + 81920;
    __half* Wn1T  = p_wT + 98304;    // [256,128]
    __half* Wn2T  = p_wT + 131072;   // [128,256]
    __half* We1T  = p_wT + 163840;
    __half* We2T  = p_wT + 196608;

    dim3 blk(256);
    dim3 tblk(32, 8);

    detect_kernel<<<1, 32>>>((const int*)ei);

    {
        dim3 g44(4, 4), g84(8, 4), g48(4, 8);
        transpose_kernel<<<g44, tblk>>>(Wq,   WqkvT + 0,     128, 128);
        transpose_kernel<<<g44, tblk>>>(Wk,   WqkvT + 16384, 128, 128);
        transpose_kernel<<<g44, tblk>>>(Wv,   WqkvT + 32768, 128, 128);
        transpose_kernel<<<g44, tblk>>>(We,   WeT, 128, 128);
        transpose_kernel<<<g44, tblk>>>(Wo_n, WonT, 128, 128);
        transpose_kernel<<<g44, tblk>>>(Wo_e, WoeT, 128, 128);
        transpose_kernel<<<g84, tblk>>>(Wn1,  Wn1T, 128, 256);
        transpose_kernel<<<g48, tblk>>>(Wn2,  Wn2T, 256, 128);
        transpose_kernel<<<g84, tblk>>>(We1,  We1T, 128, 256);
        transpose_kernel<<<g48, tblk>>>(We2,  We2T, 256, 128);
    }

    ln_kernel<<<(N + 7) / 8, blk>>>(node_feats, ln1n_g, ln1n_b, p_hln, N);
    ln_kernel<<<(E + 7) / 8, blk>>>(edge_feats, ln1e_g, ln1e_b, p_eln, E);
    dist_kernel<<<(E + 255) / 256, blk>>>(coords, ei, p_dist, E);
    fill0_kernel<<<(int)(((size_t)N * 128 + 255) / 256), blk>>>(p_wV, (size_t)N * 128);
    fill0_kernel<<<(int)(((size_t)N * 8 + 255) / 256), blk>>>(p_z, (size_t)N * 8);

    const int gN = (N + 127) / 128;
    const int gE = (E + 127) / 128;

    // qkv fused: [N,128]h @ [128,384] -> half
    mma_gemm<true><<<dim3(gN, 3), blk>>>(p_hln, 128, WqkvT, nullptr, p_qkv,
                                         N, 128, 384, nullptr, nullptr, 0, nullptr, nullptr, 0);

    // ep = LN(e) @ We[0:128] + dist (x) We[128]  -> fp32
    mma_gemm<true><<<dim3(gE, 1), blk>>>(p_eln, 128, WeT, p_ep, nullptr,
                                         E, 128, 128, nullptr, nullptr, 0,
                                         p_dist, We + 128 * 128, 0);

    attn_edge_kernel<<<(E + 7) / 8, blk>>>(p_qkv, p_ep, ei, p_wV, p_z, E);
    hattn_kernel<<<(N * 128 + 255) / 256, blk>>>(p_wV, p_z, p_hln, N);

    // h2 = node_feats + h_attn @ Wo_n + bo_n
    mma_gemm<true><<<dim3(gN, 1), blk>>>(p_hln, 128, WonT, out_n, nullptr,
                                         N, 128, 128, bo_n, node_feats, 128,
                                         nullptr, nullptr, 0);
    // e2 = edge_feats + alpha @ Wo_e + bo_e   (alpha is fp32)
    mma_gemm<false><<<dim3(gE, 1), blk>>>(p_ep, 128, WoeT, out_e, nullptr,
                                          E, 128, 128, bo_e, edge_feats, 128,
                                          nullptr, nullptr, 0);

    // node FFN
    ln_kernel<<<(N + 7) / 8, blk>>>(out_n, ln2n_g, ln2n_b, p_hln, N);
    mma_gemm<true><<<dim3(gN, 2), blk>>>(p_hln, 128, Wn1T, nullptr, p_t,
                                         N, 128, 256, nullptr, nullptr, 0,
                                         nullptr, nullptr, 1);
    mma_gemm<true><<<dim3(gN, 1), blk>>>(p_t, 256, Wn2T, out_n, nullptr,
                                         N, 256, 128, nullptr, out_n, 128,
                                         nullptr, nullptr, 0);

    // edge FFN
    ln_kernel<<<(E + 7) / 8, blk>>>(out_e, ln2e_g, ln2e_b, p_eln, E);
    mma_gemm<true><<<dim3(gE, 2), blk>>>(p_eln, 128, We1T, nullptr, p_t,
                                         E, 128, 256, nullptr, nullptr, 0,
                                         nullptr, nullptr, 1);
    mma_gemm<true><<<dim3(gE, 1), blk>>>(p_t, 256, We2T, out_e, nullptr,
                                         E, 256, 128, nullptr, out_e, 128,
                                         nullptr, nullptr, 0);
}

// round 6
// speedup vs baseline: 2.9193x; 1.0565x over previous
#include <cuda_runtime.h>
#include <cuda_fp16.h>
#include <math.h>
#include <stdint.h>

// ---------------------------------------------------------------------------
// GraphTransformer layer: N=50000, E=600000, C=128, H=8, Dh=16
// Round 6: fp16 HMMA + cp.async; alpha stored half; LN2 fused into the
// Wo_n / Wo_e GEMM epilogues (in-place over A); batched transposes.
// ---------------------------------------------------------------------------

#define N_MAX 50000
#define E_MAX 600000

__device__ __half g_hln[(size_t)N_MAX * 128];   // ln1n / h_attn / ln2n (half)
__device__ __half g_qkv[(size_t)N_MAX * 384];   // q|k|v (half)
__device__ __half g_eln[(size_t)E_MAX * 128];   // ln1e / alpha / ln2e (half)
__device__ float  g_ep [(size_t)E_MAX * 128];   // ep (fp32)
__device__ float  g_dist[(size_t)E_MAX];
__device__ float  g_wV [(size_t)N_MAX * 128];
__device__ float  g_z  [(size_t)N_MAX * 8];
__device__ __half g_t  [(size_t)E_MAX * 256];   // FFN hidden (half)
__device__ __half g_wT [229376];                // transposed half weights
__device__ int    g_is64;

// ---------------------------------------------------------------------------
// MMA + cp.async primitives (sm_80-compatible PTX)
// ---------------------------------------------------------------------------
__device__ __forceinline__ void mma_f16(float* c, const uint32_t* a,
                                        uint32_t b0, uint32_t b1) {
    asm volatile(
        "mma.sync.aligned.m16n8k16.row.col.f32.f16.f16.f32 "
        "{%0,%1,%2,%3}, {%4,%5,%6,%7}, {%8,%9}, {%0,%1,%2,%3};"
        : "+f"(c[0]), "+f"(c[1]), "+f"(c[2]), "+f"(c[3])
        : "r"(a[0]), "r"(a[1]), "r"(a[2]), "r"(a[3]), "r"(b0), "r"(b1));
}
#define CP16(d, s, n) asm volatile("cp.async.cg.shared.global [%0], [%1], 16, %2;" :: "r"(d), "l"(s), "r"(n) : "memory")
#define CPCOMMIT()    asm volatile("cp.async.commit_group;" ::: "memory")
#define CPWAIT(n)     asm volatile("cp.async.wait_group %0;" :: "n"(n) : "memory")

#define SKH 40
#define BUFB (128 * SKH * 2)

// ---------------------------------------------------------------------------
// fp16 HMMA GEMM, CTA tile 128x128, BK=32, 8 warps (4x2), double-buffered.
// Epilogues: +bias, +r1m[m]*r1n[n], SiLU, +resid; optional fused LayerNorm:
// writes fp32 result to Cf AND LN(result) as half to lnout (requires
// gridDim.y == 1 so the CTA owns full rows).
// ---------------------------------------------------------------------------
__global__ void __launch_bounds__(256, 2) mma_gemm(
    const __half* __restrict__ Ah, int lda,
    const __half* __restrict__ BT,
    float* __restrict__ Cf, __half* __restrict__ Ch,
    int M, int K, int ldc,
    const float* __restrict__ bias,
    const float* __restrict__ resid, int ldr,
    const float* __restrict__ r1m, const float* __restrict__ r1n,
    int act,
    const float* __restrict__ lng, const float* __restrict__ lnb,
    __half* __restrict__ lnout)
{
    __shared__ __half sA[2][128 * SKH];
    __shared__ __half sB[2][128 * SKH];
    __shared__ float red[128][2][2];

    const int tid = threadIdx.x;
    const int wid = tid >> 5;
    const int lane = tid & 31;
    const int warp_m = wid & 3;
    const int warp_n = wid >> 2;
    const int m0 = blockIdx.x * 128;
    const int n0 = blockIdx.y * 128;
    const int grp = lane >> 2;
    const int tig = lane & 3;

    const uint32_t sA0 = (uint32_t)__cvta_generic_to_shared(&sA[0][0]);
    const uint32_t sB0 = (uint32_t)__cvta_generic_to_shared(&sB[0][0]);

    const int arow = tid >> 2, aj = tid & 3;

    float acc[2][8][4];
    #pragma unroll
    for (int t = 0; t < 2; t++)
        #pragma unroll
        for (int j = 0; j < 8; j++)
            #pragma unroll
            for (int c = 0; c < 4; c++) acc[t][j][c] = 0.0f;

    const int nc = K >> 5;

    auto loadB = [&](int c, int buf) {
        const int k0 = c << 5;
        #pragma unroll
        for (int i = 0; i < 2; i++) {
            const int row = arow + i * 64;
            const uint32_t dst = sB0 + buf * BUFB + row * (SKH * 2) + aj * 16;
            const __half* src = BT + (size_t)(n0 + row) * K + k0 + aj * 8;
            CP16(dst, src, 16);
        }
    };
    auto loadA = [&](int c, int buf) {
        const int k0 = c << 5;
        #pragma unroll
        for (int i = 0; i < 2; i++) {
            const int row = arow + i * 64;
            const uint32_t dst = sA0 + buf * BUFB + row * (SKH * 2) + aj * 16;
            const int ok = (m0 + row) < M;
            const __half* src = Ah + (size_t)(ok ? (m0 + row) : 0) * lda + k0 + aj * 8;
            CP16(dst, src, ok ? 16 : 0);
        }
    };
    auto compute = [&](int buf) {
        const __half* Ab = &sA[buf][0];
        const __half* Bb = &sB[buf][0];
        #pragma unroll
        for (int ks = 0; ks < 2; ks++) {
            const int kk = ks * 16;
            uint32_t a[2][4];
            #pragma unroll
            for (int t = 0; t < 2; t++) {
                const __half* ap = Ab + (warp_m * 32 + t * 16 + grp) * SKH + kk + 2 * tig;
                a[t][0] = *(const uint32_t*)(ap);
                a[t][1] = *(const uint32_t*)(ap + 8 * SKH);
                a[t][2] = *(const uint32_t*)(ap + 8);
                a[t][3] = *(const uint32_t*)(ap + 8 * SKH + 8);
            }
            #pragma unroll
            for (int j = 0; j < 8; j++) {
                const __half* bp = Bb + (warp_n * 64 + j * 8 + grp) * SKH + kk + 2 * tig;
                const uint32_t b0 = *(const uint32_t*)(bp);
                const uint32_t b1 = *(const uint32_t*)(bp + 8);
                mma_f16(acc[0][j], a[0], b0, b1);
                mma_f16(acc[1][j], a[1], b0, b1);
            }
        }
    };

    loadA(0, 0); loadB(0, 0); CPCOMMIT();
    for (int c = 0; c < nc; c++) {
        if (c + 1 < nc) {
            loadA(c + 1, (c + 1) & 1); loadB(c + 1, (c + 1) & 1);
            CPCOMMIT(); CPWAIT(1);
        } else CPWAIT(0);
        __syncthreads();
        compute(c & 1);
        __syncthreads();
    }

    if (lng == nullptr) {
        // ---- plain epilogue ----
        #pragma unroll
        for (int t = 0; t < 2; t++) {
            #pragma unroll
            for (int hh = 0; hh < 2; hh++) {
                const int m = m0 + warp_m * 32 + t * 16 + grp + hh * 8;
                if (m >= M) continue;
                const float r1 = r1m ? r1m[m] : 0.0f;
                const float* rrow = resid ? resid + (size_t)m * ldr : nullptr;
                #pragma unroll
                for (int j = 0; j < 8; j++) {
                    const int col = n0 + warp_n * 64 + j * 8 + tig * 2;
                    float v0 = acc[t][j][hh * 2 + 0];
                    float v1 = acc[t][j][hh * 2 + 1];
                    if (bias) { v0 += bias[col]; v1 += bias[col + 1]; }
                    if (r1m)  { v0 += r1 * r1n[col]; v1 += r1 * r1n[col + 1]; }
                    if (act) {
                        v0 = v0 / (1.0f + expf(-v0));
                        v1 = v1 / (1.0f + expf(-v1));
                    }
                    if (resid) { v0 += rrow[col]; v1 += rrow[col + 1]; }
                    if (Ch) {
                        *(__half2*)(Ch + (size_t)m * ldc + col) = __floats2half2_rn(v0, v1);
                    } else {
                        float2 o2; o2.x = v0; o2.y = v1;
                        *(float2*)(Cf + (size_t)m * ldc + col) = o2;
                    }
                }
            }
        }
    } else {
        // ---- fused bias+resid, fp32 store, LayerNorm -> half lnout ----
        float s[2][2], sq[2][2];
        #pragma unroll
        for (int t = 0; t < 2; t++) {
            #pragma unroll
            for (int hh = 0; hh < 2; hh++) {
                const int m = m0 + warp_m * 32 + t * 16 + grp + hh * 8;
                const bool ok = m < M;
                const float* rrow = ok ? resid + (size_t)m * ldr : nullptr;
                float sum = 0.f, sumsq = 0.f;
                #pragma unroll
                for (int j = 0; j < 8; j++) {
                    const int col = warp_n * 64 + j * 8 + tig * 2;
                    float v0 = acc[t][j][hh * 2 + 0] + bias[col];
                    float v1 = acc[t][j][hh * 2 + 1] + bias[col + 1];
                    if (ok) { v0 += rrow[col]; v1 += rrow[col + 1]; }
                    acc[t][j][hh * 2 + 0] = v0;
                    acc[t][j][hh * 2 + 1] = v1;
                    if (ok) {
                        float2 o2; o2.x = v0; o2.y = v1;
                        *(float2*)(Cf + (size_t)m * ldc + col) = o2;
                    }
                    sum += v0 + v1;
                    sumsq += v0 * v0 + v1 * v1;
                }
                s[t][hh] = sum; sq[t][hh] = sumsq;
            }
        }
        // reduce over the 4-thread quad (lane bits 0..1)
        #pragma unroll
        for (int t = 0; t < 2; t++)
            #pragma unroll
            for (int hh = 0; hh < 2; hh++) {
                s[t][hh]  += __shfl_xor_sync(0xffffffffu, s[t][hh], 1);
                s[t][hh]  += __shfl_xor_sync(0xffffffffu, s[t][hh], 2);
                sq[t][hh] += __shfl_xor_sync(0xffffffffu, sq[t][hh], 1);
                sq[t][hh] += __shfl_xor_sync(0xffffffffu, sq[t][hh], 2);
            }
        if (tig == 0) {
            #pragma unroll
            for (int t = 0; t < 2; t++)
                #pragma unroll
                for (int hh = 0; hh < 2; hh++) {
                    const int row = warp_m * 32 + t * 16 + hh * 8 + grp;
                    red[row][warp_n][0] = s[t][hh];
                    red[row][warp_n][1] = sq[t][hh];
                }
        }
        __syncthreads();
        #pragma unroll
        for (int t = 0; t < 2; t++) {
            #pragma unroll
            for (int hh = 0; hh < 2; hh++) {
                const int row = warp_m * 32 + t * 16 + hh * 8 + grp;
                const int m = m0 + row;
                if (m >= M) continue;
                const float S = red[row][0][0] + red[row][1][0];
                const float Q = red[row][0][1] + red[row][1][1];
                const float mu = S * (1.0f / 128.0f);
                const float var = Q * (1.0f / 128.0f) - mu * mu;
                const float rs = rsqrtf(var + 1e-5f);
                #pragma unroll
                for (int j = 0; j < 8; j++) {
                    const int col = warp_n * 64 + j * 8 + tig * 2;
                    float v0 = (acc[t][j][hh * 2 + 0] - mu) * rs * lng[col] + lnb[col];
                    float v1 = (acc[t][j][hh * 2 + 1] - mu) * rs * lng[col + 1] + lnb[col + 1];
                    *(__half2*)(lnout + (size_t)m * 128 + col) = __floats2half2_rn(v0, v1);
                }
            }
        }
    }
}

// ---------------------------------------------------------------------------
// Batched weight transpose to half: ten src[R,C] fp32 -> dst[C,R] half
// ---------------------------------------------------------------------------
struct TransBatch {
    const float* src[10];
    __half* dst[10];
    int R[10], C[10];
};

__global__ void transpose_all(TransBatch tb)
{
    __shared__ float tile[32][33];
    const int i = blockIdx.z;
    const int R = tb.R[i], Cc = tb.C[i];
    const int c0 = blockIdx.x * 32, r0 = blockIdx.y * 32;
    if (c0 >= Cc || r0 >= R) return;
    const float* src = tb.src[i];
    __half* dst = tb.dst[i];
    int tx = threadIdx.x, ty = threadIdx.y;
    for (int dy = 0; dy < 32; dy += 8) {
        int r = r0 + ty + dy, c = c0 + tx;
        if (r < R && c < Cc) tile[ty + dy][tx] = src[(size_t)r * Cc + c];
    }
    __syncthreads();
    for (int dy = 0; dy < 32; dy += 8) {
        int c = c0 + ty + dy, r = r0 + tx;
        if (r < R && c < Cc) dst[(size_t)c * R + r] = __float2half_rn(tile[tx][ty + dy]);
    }
}

// ---------------------------------------------------------------------------
// misc kernels
// ---------------------------------------------------------------------------
__global__ void detect_kernel(const int* __restrict__ ei32)
{
    if (threadIdx.x == 0 && blockIdx.x == 0) {
        int any = 0;
        #pragma unroll 8
        for (int i = 0; i < 64; i++) any |= ei32[2 * i + 1];
        g_is64 = (any == 0) ? 1 : 0;
    }
}
__device__ __forceinline__ int edge_idx(const void* __restrict__ ei, long long pos)
{
    if (g_is64) return (int)((const long long*)ei)[pos];
    return ((const int*)ei)[pos];
}

__global__ void ln_kernel(const float* __restrict__ x,
                          const float* __restrict__ g,
                          const float* __restrict__ b,
                          __half* __restrict__ out, int M)
{
    int w = (blockIdx.x * blockDim.x + threadIdx.x) >> 5;
    int lane = threadIdx.x & 31;
    if (w >= M) return;
    float4 v = *(const float4*)(x + (size_t)w * 128 + lane * 4);
    float s  = v.x + v.y + v.z + v.w;
    float sq = v.x*v.x + v.y*v.y + v.z*v.z + v.w*v.w;
    #pragma unroll
    for (int o = 16; o; o >>= 1) {
        s  += __shfl_xor_sync(0xffffffffu, s,  o);
        sq += __shfl_xor_sync(0xffffffffu, sq, o);
    }
    float mu  = s * (1.0f / 128.0f);
    float var = sq * (1.0f / 128.0f) - mu * mu;
    float rs  = rsqrtf(var + 1e-5f);
    float4 gv = *(const float4*)(g + lane * 4);
    float4 bv = *(const float4*)(b + lane * 4);
    __half2 h0 = __floats2half2_rn((v.x - mu) * rs * gv.x + bv.x,
                                   (v.y - mu) * rs * gv.y + bv.y);
    __half2 h1 = __floats2half2_rn((v.z - mu) * rs * gv.z + bv.z,
                                   (v.w - mu) * rs * gv.w + bv.w);
    uint2 u; u.x = *(uint32_t*)&h0; u.y = *(uint32_t*)&h1;
    *(uint2*)(out + (size_t)w * 128 + lane * 4) = u;
}

__global__ void dist_kernel(const float* __restrict__ coords,
                            const void* __restrict__ ei,
                            float* __restrict__ dist, int E)
{
    int e = blockIdx.x * blockDim.x + threadIdx.x;
    if (e >= E) return;
    int r = edge_idx(ei, e);
    int c = edge_idx(ei, (long long)E + e);
    float dx = coords[r * 3 + 0] - coords[c * 3 + 0];
    float dy = coords[r * 3 + 1] - coords[c * 3 + 1];
    float dz = coords[r * 3 + 2] - coords[c * 3 + 2];
    dist[e] = 0.1f * sqrtf(dx * dx + dy * dy + dz * dz);
}

__global__ void fill0_2(float* __restrict__ p1, size_t n1,
                        float* __restrict__ p2, size_t n2)
{
    size_t i = (size_t)blockIdx.x * blockDim.x + threadIdx.x;
    if (i < n1) p1[i] = 0.0f;
    else if (i < n1 + n2) p2[i - n1] = 0.0f;
}

__device__ __forceinline__ float4 ld_half4(const __half* p)
{
    uint2 u = *(const uint2*)p;
    __half2 h0 = *(__half2*)&u.x, h1 = *(__half2*)&u.y;
    float2 f0 = __half22float2(h0), f1 = __half22float2(h1);
    return make_float4(f0.x, f0.y, f1.x, f1.y);
}

// edge attention: one warp per edge; ep fp32 in, alpha half out
__global__ void attn_edge_kernel(const __half* __restrict__ qkv,
                                 const float* __restrict__ ep,
                                 __half* __restrict__ alpha_h,
                                 const void* __restrict__ ei,
                                 float* __restrict__ wV,
                                 float* __restrict__ z,
                                 int E)
{
    int w = (blockIdx.x * blockDim.x + threadIdx.x) >> 5;
    int lane = threadIdx.x & 31;
    if (w >= E) return;
    int r = edge_idx(ei, w);
    int c = edge_idx(ei, (long long)E + w);

    float4 q4 = ld_half4(qkv + (size_t)c * 384 + lane * 4);
    float4 k4 = ld_half4(qkv + (size_t)r * 384 + 128 + lane * 4);
    float4 v4 = ld_half4(qkv + (size_t)r * 384 + 256 + lane * 4);
    float4 e4 = *(const float4*)(ep + (size_t)w * 128 + lane * 4);

    float4 a4;
    a4.x = fminf(fmaxf(k4.x * q4.x * 0.25f, -5.0f), 5.0f) * e4.x;
    a4.y = fminf(fmaxf(k4.y * q4.y * 0.25f, -5.0f), 5.0f) * e4.y;
    a4.z = fminf(fmaxf(k4.z * q4.z * 0.25f, -5.0f), 5.0f) * e4.z;
    a4.w = fminf(fmaxf(k4.w * q4.w * 0.25f, -5.0f), 5.0f) * e4.w;

    __half2 p0 = __floats2half2_rn(a4.x, a4.y);
    __half2 p1 = __floats2half2_rn(a4.z, a4.w);
    uint2 u; u.x = *(uint32_t*)&p0; u.y = *(uint32_t*)&p1;
    *(uint2*)(alpha_h + (size_t)w * 128 + lane * 4) = u;

    float hs = a4.x + a4.y + a4.z + a4.w;
    hs += __shfl_xor_sync(0xffffffffu, hs, 1);
    hs += __shfl_xor_sync(0xffffffffu, hs, 2);
    float ax = expf(fminf(fmaxf(hs, -5.0f), 5.0f));

    float* wvp = wV + (size_t)c * 128 + lane * 4;
    atomicAdd(wvp + 0, v4.x * ax);
    atomicAdd(wvp + 1, v4.y * ax);
    atomicAdd(wvp + 2, v4.z * ax);
    atomicAdd(wvp + 3, v4.w * ax);
    if ((lane & 3) == 0)
        atomicAdd(z + (size_t)c * 8 + (lane >> 2), ax);
}

__global__ void hattn_kernel(const float* __restrict__ wV,
                             const float* __restrict__ z,
                             __half* __restrict__ out, int N)
{
    int i = blockIdx.x * blockDim.x + threadIdx.x;
    if (i >= N * 128) return;
    int n = i >> 7;
    int h = (i & 127) >> 4;
    out[i] = __float2half_rn(wV[i] / (z[(size_t)n * 8 + h] + 1e-6f));
}

// ---------------------------------------------------------------------------
// Launch
// ---------------------------------------------------------------------------
extern "C" void kernel_launch(void* const* d_in, const int* in_sizes, int n_in,
                              void* d_out, int out_size)
{
    const float* node_feats = (const float*)d_in[0];
    const float* edge_feats = (const float*)d_in[1];
    const float* coords     = (const float*)d_in[2];
    const void*  ei         = d_in[3];
    const float* Wq   = (const float*)d_in[4];
    const float* Wk   = (const float*)d_in[5];
    const float* Wv   = (const float*)d_in[6];
    const float* We   = (const float*)d_in[7];
    const float* Wo_n = (const float*)d_in[8];
    const float* bo_n = (const float*)d_in[9];
    const float* Wo_e = (const float*)d_in[10];
    const float* bo_e = (const float*)d_in[11];
    const float* ln1n_g = (const float*)d_in[12];
    const float* ln1n_b = (const float*)d_in[13];
    const float* ln1e_g = (const float*)d_in[14];
    const float* ln1e_b = (const float*)d_in[15];
    const float* ln2n_g = (const float*)d_in[16];
    const float* ln2n_b = (const float*)d_in[17];
    const float* ln2e_g = (const float*)d_in[18];
    const float* ln2e_b = (const float*)d_in[19];
    const float* Wn1 = (const float*)d_in[20];
    const float* Wn2 = (const float*)d_in[21];
    const float* We1 = (const float*)d_in[22];
    const float* We2 = (const float*)d_in[23];

    int N = in_sizes[0] / 128;
    int E = in_sizes[1] / 128;

    float* out   = (float*)d_out;
    float* out_n = out;
    float* out_e = out + (size_t)N * 128;

    __half *p_hln, *p_qkv, *p_eln, *p_t, *p_wT;
    float *p_ep, *p_dist, *p_wV, *p_z;
    cudaGetSymbolAddress((void**)&p_hln,  g_hln);
    cudaGetSymbolAddress((void**)&p_qkv,  g_qkv);
    cudaGetSymbolAddress((void**)&p_eln,  g_eln);
    cudaGetSymbolAddress((void**)&p_ep,   g_ep);
    cudaGetSymbolAddress((void**)&p_dist, g_dist);
    cudaGetSymbolAddress((void**)&p_wV,   g_wV);
    cudaGetSymbolAddress((void**)&p_z,    g_z);
    cudaGetSymbolAddress((void**)&p_t,    g_t);
    cudaGetSymbolAddress((void**)&p_wT,   g_wT);

    __half* WqkvT = p_wT + 0;        // [384,128]
    __half* WeT   = p_wT + 49152;    // [128,128]
    __half* WonT  = p_wT + 65536;
    __half* WoeT  = p_wT + 81920;
    __half* Wn1T  = p_wT + 98304;    // [256,128]
    __half* Wn2T  = p_wT + 131072;   // [128,256]
    __half* We1T  = p_wT + 163840;
    __half* We2T  = p_wT + 196608;

    dim3 blk(256);

    detect_kernel<<<1, 32>>>((const int*)ei);

    // batched transposes (one launch)
    {
        TransBatch tb;
        const float* srcs[10] = {Wq, Wk, Wv, We, Wo_n, Wo_e, Wn1, Wn2, We1, We2};
        __half* dsts[10] = {WqkvT, WqkvT + 16384, WqkvT + 32768, WeT, WonT, WoeT,
                            Wn1T, Wn2T, We1T, We2T};
        int Rs[10] = {128, 128, 128, 128, 128, 128, 128, 256, 128, 256};
        int Cs[10] = {128, 128, 128, 128, 128, 128, 256, 128, 256, 128};
        for (int i = 0; i < 10; i++) {
            tb.src[i] = srcs[i]; tb.dst[i] = dsts[i]; tb.R[i] = Rs[i]; tb.C[i] = Cs[i];
        }
        transpose_all<<<dim3(8, 8, 10), dim3(32, 8)>>>(tb);
    }

    ln_kernel<<<(N + 7) / 8, blk>>>(node_feats, ln1n_g, ln1n_b, p_hln, N);
    ln_kernel<<<(E + 7) / 8, blk>>>(edge_feats, ln1e_g, ln1e_b, p_eln, E);
    dist_kernel<<<(E + 255) / 256, blk>>>(coords, ei, p_dist, E);
    fill0_2<<<(int)(((size_t)N * 136 + 255) / 256), blk>>>(p_wV, (size_t)N * 128,
                                                           p_z, (size_t)N * 8);

    const int gN = (N + 127) / 128;
    const int gE = (E + 127) / 128;

    // qkv fused: [N,128]h @ [128,384] -> half
    mma_gemm<<<dim3(gN, 3), blk>>>(p_hln, 128, WqkvT, nullptr, p_qkv,
                                   N, 128, 384, nullptr, nullptr, 0,
                                   nullptr, nullptr, 0, nullptr, nullptr, nullptr);

    // ep = LN(e) @ We[0:128] + dist (x) We[128] -> fp32
    mma_gemm<<<dim3(gE, 1), blk>>>(p_eln, 128, WeT, p_ep, nullptr,
                                   E, 128, 128, nullptr, nullptr, 0,
                                   p_dist, We + 128 * 128, 0, nullptr, nullptr, nullptr);

    // attention: alpha (half) into p_eln; atomics into wV, z
    attn_edge_kernel<<<(E + 7) / 8, blk>>>(p_qkv, p_ep, p_eln, ei, p_wV, p_z, E);
    hattn_kernel<<<(N * 128 + 255) / 256, blk>>>(p_wV, p_z, p_hln, N);

    // h2 = node_feats + h_attn @ Wo_n + bo_n; fused LN2n -> p_hln (in-place A)
    mma_gemm<<<dim3(gN, 1), blk>>>(p_hln, 128, WonT, out_n, nullptr,
                                   N, 128, 128, bo_n, node_feats, 128,
                                   nullptr, nullptr, 0, ln2n_g, ln2n_b, p_hln);
    // e2 = edge_feats + alpha @ Wo_e + bo_e; fused LN2e -> p_eln (in-place A)
    mma_gemm<<<dim3(gE, 1), blk>>>(p_eln, 128, WoeT, out_e, nullptr,
                                   E, 128, 128, bo_e, edge_feats, 128,
                                   nullptr, nullptr, 0, ln2e_g, ln2e_b, p_eln);

    // node FFN
    mma_gemm<<<dim3(gN, 2), blk>>>(p_hln, 128, Wn1T, nullptr, p_t,
                                   N, 128, 256, nullptr, nullptr, 0,
                                   nullptr, nullptr, 1, nullptr, nullptr, nullptr);
    mma_gemm<<<dim3(gN, 1), blk>>>(p_t, 256, Wn2T, out_n, nullptr,
                                   N, 256, 128, nullptr, out_n, 128,
                                   nullptr, nullptr, 0, nullptr, nullptr, nullptr);

    // edge FFN
    mma_gemm<<<dim3(gE, 2), blk>>>(p_eln, 128, We1T, nullptr, p_t,
                                   E, 128, 256, nullptr, nullptr, 0,
                                   nullptr, nullptr, 1, nullptr, nullptr, nullptr);
    mma_gemm<<<dim3(gE, 1), blk>>>(p_t, 256, We2T, out_e, nullptr,
                                   E, 256, 128, nullptr, out_e, 128,
                                   nullptr, nullptr, 0, nullptr, nullptr, nullptr);
}